// round 9
// baseline (speedup 1.0000x reference)
#include <cuda_runtime.h>
#include <cuda_bf16.h>
#include <cstdint>

#define BATCH 4
#define CDIM 256
#define NDIM 4096
#define SM_SHIFT 20.0f

// ---------------- scratch (__device__ globals; no allocs allowed) ----------
__device__ __nv_bfloat16 g_W_hi [320 * CDIM];
__device__ __nv_bfloat16 g_W_lo [320 * CDIM];
__device__ __nv_bfloat16 g_x_hi [(size_t)BATCH * CDIM * NDIM];
__device__ __nv_bfloat16 g_x_lo [(size_t)BATCH * CDIM * NDIM];
__device__ __nv_bfloat16 g_fT_hi[(size_t)BATCH * NDIM * 32];
__device__ __nv_bfloat16 g_fT_lo[(size_t)BATCH * NDIM * 32];
__device__ __nv_bfloat16 g_g_hi [(size_t)BATCH * 32 * NDIM];
__device__ __nv_bfloat16 g_g_lo [(size_t)BATCH * 32 * NDIM];
__device__ __nv_bfloat16 g_h    [(size_t)BATCH * CDIM * NDIM]; // h, later h/r
__device__ __nv_bfloat16 g_E    [(size_t)BATCH * NDIM * NDIM]; // exp(S-20) bf16
__device__ float         g_r    [(size_t)BATCH * NDIM];        // row sums

// ---------------- asm helpers ----------------------------------------------
#define CP_ASYNC16(dst, src) \
    asm volatile("cp.async.cg.shared.global [%0], [%1], 16;\n" ::"r"(dst), "l"(src))
#define CP_COMMIT asm volatile("cp.async.commit_group;\n")
#define CP_WAIT(n) asm volatile("cp.async.wait_group %0;\n" ::"n"(n))

#define LDSM_X4(r0, r1, r2, r3, addr)                                          \
    asm volatile("ldmatrix.sync.aligned.m8n8.x4.shared.b16 {%0,%1,%2,%3}, [%4];" \
                 : "=r"(r0), "=r"(r1), "=r"(r2), "=r"(r3) : "r"(addr))
#define LDSM_X4T(r0, r1, r2, r3, addr)                                         \
    asm volatile("ldmatrix.sync.aligned.m8n8.x4.trans.shared.b16 {%0,%1,%2,%3}, [%4];" \
                 : "=r"(r0), "=r"(r1), "=r"(r2), "=r"(r3) : "r"(addr))

#define MMA16816(d, a, b0, b1)                                                 \
    asm volatile(                                                              \
        "mma.sync.aligned.m16n8k16.row.col.f32.bf16.bf16.f32 "                 \
        "{%0,%1,%2,%3}, {%4,%5,%6,%7}, {%8,%9}, {%0,%1,%2,%3};"                \
        : "+f"(d[0]), "+f"(d[1]), "+f"(d[2]), "+f"(d[3])                       \
        : "r"(a[0]), "r"(a[1]), "r"(a[2]), "r"(a[3]), "r"(b0), "r"(b1))

__device__ __forceinline__ void split_hl(float v, __nv_bfloat16& hi, __nv_bfloat16& lo) {
    hi = __float2bfloat16(v);
    lo = __float2bfloat16(v - __bfloat162float(hi));
}

// ---------------------------------------------------------------------------
// kPrep: fused x hi/lo conversion (all 4096 blocks) + W conversion (blocks
// 0-319) + r zero-init (blocks 320-383).
// ---------------------------------------------------------------------------
__global__ __launch_bounds__(256)
void kPrep(const float* __restrict__ x,
           const float* __restrict__ Wf, const float* __restrict__ Wg,
           const float* __restrict__ Wh) {
    const int tid = threadIdx.x, bid = blockIdx.x;

    size_t i4 = ((size_t)bid * 256 + tid) * 4;
    float4 v = *(const float4*)&x[i4];
    __nv_bfloat16 h0, l0, h1, l1, h2, l2, h3, l3;
    split_hl(v.x, h0, l0); split_hl(v.y, h1, l1);
    split_hl(v.z, h2, l2); split_hl(v.w, h3, l3);
    __nv_bfloat162* ph = (__nv_bfloat162*)&g_x_hi[i4];
    __nv_bfloat162* pl = (__nv_bfloat162*)&g_x_lo[i4];
    ph[0] = __nv_bfloat162{h0, h1}; ph[1] = __nv_bfloat162{h2, h3};
    pl[0] = __nv_bfloat162{l0, l1}; pl[1] = __nv_bfloat162{l2, l3};

    if (bid < 320) {
        int idx = bid * 256 + tid;
        int r = idx >> 8, c = idx & 255;
        float w = (r < 32) ? Wf[r * CDIM + c]
                : (r < 64) ? Wg[(r - 32) * CDIM + c]
                           : Wh[(r - 64) * CDIM + c];
        __nv_bfloat16 hi, lo;
        split_hl(w, hi, lo);
        g_W_hi[idx] = hi;
        g_W_lo[idx] = lo;
    } else if (bid < 384) {
        g_r[(bid - 320) * 256 + tid] = 0.f;
    }
}

// ---------------------------------------------------------------------------
// k1_tc: projection on tensor cores with hi/lo split (unchanged from R7).
// ---------------------------------------------------------------------------
#define P_LDA 40
#define P_LDB 136

__global__ __launch_bounds__(256)
void k1_tc(const float* __restrict__ bf, const float* __restrict__ bg,
           const float* __restrict__ bh) {
    const int b  = blockIdx.z;
    const int o0 = blockIdx.y * 64;
    const int n0 = blockIdx.x * 128;

    __shared__ __nv_bfloat16 Whs[2][64 * P_LDA];
    __shared__ __nv_bfloat16 Wls[2][64 * P_LDA];
    __shared__ __nv_bfloat16 Xhs[2][32 * P_LDB];
    __shared__ __nv_bfloat16 Xls[2][32 * P_LDB];

    const int tid = threadIdx.x, warp = tid >> 5, lane = tid & 31;
    const int wm = warp >> 2, wn = warp & 3;

    float acc[2][4][4];
#pragma unroll
    for (int mt = 0; mt < 2; mt++)
#pragma unroll
        for (int nt = 0; nt < 4; nt++)
#pragma unroll
            for (int q = 0; q < 4; q++) acc[mt][nt][q] = 0.f;

    auto issue = [&](int kt) {
        const int buf = kt & 1, k0 = kt * 32;
        {
            int row = tid >> 2, c8 = (tid & 3) * 8;
            uint32_t dh = (uint32_t)__cvta_generic_to_shared(&Whs[buf][row * P_LDA + c8]);
            CP_ASYNC16(dh, &g_W_hi[(o0 + row) * CDIM + k0 + c8]);
            uint32_t dl = (uint32_t)__cvta_generic_to_shared(&Wls[buf][row * P_LDA + c8]);
            CP_ASYNC16(dl, &g_W_lo[(o0 + row) * CDIM + k0 + c8]);
        }
#pragma unroll
        for (int r = 0; r < 2; r++) {
            int idx = tid + r * 256;
            int row = idx >> 4, c8 = (idx & 15) * 8;
            size_t src = ((size_t)b * CDIM + k0 + row) * NDIM + n0 + c8;
            uint32_t dh = (uint32_t)__cvta_generic_to_shared(&Xhs[buf][row * P_LDB + c8]);
            CP_ASYNC16(dh, &g_x_hi[src]);
            uint32_t dl = (uint32_t)__cvta_generic_to_shared(&Xls[buf][row * P_LDB + c8]);
            CP_ASYNC16(dl, &g_x_lo[src]);
        }
        CP_COMMIT;
    };

    auto compute = [&](int buf) {
#pragma unroll
        for (int ks = 0; ks < 2; ks++) {
            uint32_t ah[2][4], al[2][4], bh[4][2], bl[4][2];
#pragma unroll
            for (int mt = 0; mt < 2; mt++) {
                uint32_t ad = (uint32_t)__cvta_generic_to_shared(
                    &Whs[buf][(wm * 32 + mt * 16 + (lane & 15)) * P_LDA + ks * 16 + (lane >> 4) * 8]);
                LDSM_X4(ah[mt][0], ah[mt][1], ah[mt][2], ah[mt][3], ad);
                uint32_t ad2 = (uint32_t)__cvta_generic_to_shared(
                    &Wls[buf][(wm * 32 + mt * 16 + (lane & 15)) * P_LDA + ks * 16 + (lane >> 4) * 8]);
                LDSM_X4(al[mt][0], al[mt][1], al[mt][2], al[mt][3], ad2);
            }
#pragma unroll
            for (int np = 0; np < 2; np++) {
                uint32_t r0, r1, r2, r3;
                uint32_t bd = (uint32_t)__cvta_generic_to_shared(
                    &Xhs[buf][(ks * 16 + (lane & 15)) * P_LDB + wn * 32 + np * 16 + (lane >> 4) * 8]);
                LDSM_X4T(r0, r1, r2, r3, bd);
                bh[2 * np][0] = r0;     bh[2 * np][1] = r1;
                bh[2 * np + 1][0] = r2; bh[2 * np + 1][1] = r3;
                uint32_t bd2 = (uint32_t)__cvta_generic_to_shared(
                    &Xls[buf][(ks * 16 + (lane & 15)) * P_LDB + wn * 32 + np * 16 + (lane >> 4) * 8]);
                LDSM_X4T(r0, r1, r2, r3, bd2);
                bl[2 * np][0] = r0;     bl[2 * np][1] = r1;
                bl[2 * np + 1][0] = r2; bl[2 * np + 1][1] = r3;
            }
#pragma unroll
            for (int mt = 0; mt < 2; mt++)
#pragma unroll
                for (int nt = 0; nt < 4; nt++) {
                    MMA16816(acc[mt][nt], ah[mt], bh[nt][0], bh[nt][1]);
                    MMA16816(acc[mt][nt], ah[mt], bl[nt][0], bl[nt][1]);
                    MMA16816(acc[mt][nt], al[mt], bh[nt][0], bh[nt][1]);
                }
        }
    };

    const int KT = CDIM / 32;
    issue(0);
    for (int kt = 0; kt < KT; kt++) {
        if (kt + 1 < KT) issue(kt + 1);
        if (kt + 1 < KT) { CP_WAIT(1); } else { CP_WAIT(0); }
        __syncthreads();
        compute(kt & 1);
        __syncthreads();
    }

#pragma unroll
    for (int mt = 0; mt < 2; mt++) {
#pragma unroll
        for (int nt = 0; nt < 4; nt++) {
#pragma unroll
            for (int half = 0; half < 2; half++) {
                int o = o0 + wm * 32 + mt * 16 + (lane >> 2) + half * 8;
                int n = n0 + wn * 32 + nt * 8 + (lane & 3) * 2;
                float v0 = acc[mt][nt][half * 2];
                float v1 = acc[mt][nt][half * 2 + 1];
                if (o < 32) {
                    float bias = bf[o];
                    __nv_bfloat16 h0, l0, h1, l1;
                    split_hl(v0 + bias, h0, l0);
                    split_hl(v1 + bias, h1, l1);
                    size_t base = (size_t)(b * NDIM + n) * 32 + o;
                    g_fT_hi[base] = h0;      g_fT_lo[base] = l0;
                    g_fT_hi[base + 32] = h1; g_fT_lo[base + 32] = l1;
                } else if (o < 64) {
                    float bias = bg[o - 32];
                    __nv_bfloat16 h0, l0, h1, l1;
                    split_hl(v0 + bias, h0, l0);
                    split_hl(v1 + bias, h1, l1);
                    size_t base = ((size_t)b * 32 + (o - 32)) * NDIM + n;
                    *(__nv_bfloat162*)&g_g_hi[base] = __nv_bfloat162{h0, h1};
                    *(__nv_bfloat162*)&g_g_lo[base] = __nv_bfloat162{l0, l1};
                } else {
                    float bias = bh[o - 64];
                    size_t base = ((size_t)b * CDIM + (o - 64)) * NDIM + n;
                    *(__nv_bfloat162*)&g_h[base] =
                        __floats2bfloat162_rn(v0 + bias, v1 + bias);
                }
            }
        }
    }
}

// ---------------------------------------------------------------------------
// k23_single: one pass, E + row sums. 3-stage cp.async (dynamic smem),
// issue-after-sync, single barrier per chunk. grid (2, 32, B).
// ---------------------------------------------------------------------------
#define FJ_LDA 40
#define FJ_LDB 136
#define FJ_A_ELEMS (128 * FJ_LDA)
#define FJ_G_ELEMS (32 * FJ_LDB)
#define FJ_SMEM_BYTES ((FJ_A_ELEMS + 6 * FJ_G_ELEMS) * 2)

__global__ __launch_bounds__(256)
void k23_single() {
    const int b    = blockIdx.z;
    const int n0   = blockIdx.y * 128;
    const int part = blockIdx.x;           // m chunks [part*16, part*16+16)

    extern __shared__ __nv_bfloat16 sm23[];
    __nv_bfloat16* Ahs = sm23;                         // 128*40
    __nv_bfloat16* Gh0 = sm23 + FJ_A_ELEMS;            // 3 * 32*136
    __nv_bfloat16* Gl0 = Gh0 + 3 * FJ_G_ELEMS;

    const int tid = threadIdx.x, wid = tid >> 5, lane = tid & 31;

    const __nv_bfloat16* fh = g_fT_hi + (size_t)(b * NDIM + n0) * 32;
    const __nv_bfloat16* fl = g_fT_lo + (size_t)(b * NDIM + n0) * 32;
    const __nv_bfloat16* gh = g_g_hi + (size_t)b * 32 * NDIM;
    const __nv_bfloat16* gl = g_g_lo + (size_t)b * 32 * NDIM;

    auto issue = [&](int mc) {
        const int buf = mc % 3, m0 = mc * 128;
        __nv_bfloat16* Gh = Gh0 + buf * FJ_G_ELEMS;
        __nv_bfloat16* Gl = Gl0 + buf * FJ_G_ELEMS;
#pragma unroll
        for (int r = 0; r < 2; r++) {
            int idx = tid + r * 256;
            int row = idx >> 4, c8 = (idx & 15) * 8;
            uint32_t dh = (uint32_t)__cvta_generic_to_shared(&Gh[row * FJ_LDB + c8]);
            CP_ASYNC16(dh, &gh[(size_t)row * NDIM + m0 + c8]);
            uint32_t dl = (uint32_t)__cvta_generic_to_shared(&Gl[row * FJ_LDB + c8]);
            CP_ASYNC16(dl, &gl[(size_t)row * NDIM + m0 + c8]);
        }
        CP_COMMIT;
    };

    const int mc0 = part * 16, mc1 = mc0 + 16;
    issue(mc0);
    issue(mc0 + 1);

    // stage A fragments (hi then lo through the same smem buffer)
    uint32_t ah[2][4], al[2][4];
#pragma unroll
    for (int r = 0; r < 2; r++) {
        int idx = tid + r * 256;
        int row = idx >> 2, c8 = (idx & 3) * 8;
        *(uint4*)&Ahs[row * FJ_LDA + c8] = *(const uint4*)&fh[row * 32 + c8];
    }
    __syncthreads();
#pragma unroll
    for (int kc = 0; kc < 2; kc++) {
        uint32_t addr = (uint32_t)__cvta_generic_to_shared(
            &Ahs[(wid * 16 + (lane & 15)) * FJ_LDA + kc * 16 + (lane >> 4) * 8]);
        LDSM_X4(ah[kc][0], ah[kc][1], ah[kc][2], ah[kc][3], addr);
    }
    __syncthreads();
#pragma unroll
    for (int r = 0; r < 2; r++) {
        int idx = tid + r * 256;
        int row = idx >> 2, c8 = (idx & 3) * 8;
        *(uint4*)&Ahs[row * FJ_LDA + c8] = *(const uint4*)&fl[row * 32 + c8];
    }
    __syncthreads();
#pragma unroll
    for (int kc = 0; kc < 2; kc++) {
        uint32_t addr = (uint32_t)__cvta_generic_to_shared(
            &Ahs[(wid * 16 + (lane & 15)) * FJ_LDA + kc * 16 + (lane >> 4) * 8]);
        LDSM_X4(al[kc][0], al[kc][1], al[kc][2], al[kc][3], addr);
    }

    __nv_bfloat16* Eb = g_E + (size_t)b * NDIM * NDIM;
    const int row0 = n0 + wid * 16 + (lane >> 2);
    const int colb = (lane & 3) * 2;

    float s0 = 0.f, s8 = 0.f;
    for (int mc = mc0; mc < mc1; mc++) {
        if (mc + 1 < mc1) { CP_WAIT(1); } else { CP_WAIT(0); }
        __syncthreads();
        if (mc + 2 < mc1) issue(mc + 2);

        const int buf = mc % 3;
        const __nv_bfloat16* Gh = Gh0 + buf * FJ_G_ELEMS;
        const __nv_bfloat16* Gl = Gl0 + buf * FJ_G_ELEMS;

        float acc[16][4];
#pragma unroll
        for (int nt = 0; nt < 16; nt++)
#pragma unroll
            for (int q = 0; q < 4; q++) acc[nt][q] = 0.f;
#pragma unroll
        for (int kc = 0; kc < 2; kc++) {
#pragma unroll
            for (int np = 0; np < 8; np++) {
                uint32_t bh[4], bl[4];
                uint32_t addr_h = (uint32_t)__cvta_generic_to_shared(
                    &Gh[(kc * 16 + (lane & 15)) * FJ_LDB + np * 16 + (lane >> 4) * 8]);
                LDSM_X4T(bh[0], bh[1], bh[2], bh[3], addr_h);
                uint32_t addr_l = (uint32_t)__cvta_generic_to_shared(
                    &Gl[(kc * 16 + (lane & 15)) * FJ_LDB + np * 16 + (lane >> 4) * 8]);
                LDSM_X4T(bl[0], bl[1], bl[2], bl[3], addr_l);
#pragma unroll
                for (int t = 0; t < 2; t++) {
                    const int nt = np * 2 + t;
                    MMA16816(acc[nt], ah[kc], bh[2 * t], bh[2 * t + 1]);
                    MMA16816(acc[nt], ah[kc], bl[2 * t], bl[2 * t + 1]);
                    MMA16816(acc[nt], al[kc], bh[2 * t], bh[2 * t + 1]);
                }
            }
        }

        const int m0 = mc * 128;
#pragma unroll
        for (int nt = 0; nt < 16; nt++) {
            float e0 = __expf(acc[nt][0] - SM_SHIFT);
            float e1 = __expf(acc[nt][1] - SM_SHIFT);
            float e2 = __expf(acc[nt][2] - SM_SHIFT);
            float e3 = __expf(acc[nt][3] - SM_SHIFT);
            s0 += e0 + e1;
            s8 += e2 + e3;
            *reinterpret_cast<__nv_bfloat162*>(
                &Eb[(size_t)row0 * NDIM + m0 + nt * 8 + colb]) = __floats2bfloat162_rn(e0, e1);
            *reinterpret_cast<__nv_bfloat162*>(
                &Eb[(size_t)(row0 + 8) * NDIM + m0 + nt * 8 + colb]) = __floats2bfloat162_rn(e2, e3);
        }
    }

    s0 += __shfl_xor_sync(0xffffffffu, s0, 1);
    s0 += __shfl_xor_sync(0xffffffffu, s0, 2);
    s8 += __shfl_xor_sync(0xffffffffu, s8, 1);
    s8 += __shfl_xor_sync(0xffffffffu, s8, 2);
    if ((lane & 3) == 0) {
        atomicAdd(&g_r[(size_t)b * NDIM + row0], s0);
        atomicAdd(&g_r[(size_t)b * NDIM + row0 + 8], s8);
    }
}

// ---------------------------------------------------------------------------
// kh_scale: h[b,c,n] *= 1/r[b,n]  (in place).
// ---------------------------------------------------------------------------
__global__ __launch_bounds__(256)
void kh_scale() {
    size_t i8 = ((size_t)blockIdx.x * 256 + threadIdx.x) * 8;
    int n = (int)(i8 & (NDIM - 1));
    int b = (int)(i8 >> 20);
    const float* rp = &g_r[(size_t)b * NDIM + n];
    float4 ra = *(const float4*)rp;
    float4 rb = *(const float4*)(rp + 4);
    uint4 hv = *(uint4*)&g_h[i8];
    __nv_bfloat162* h2 = (__nv_bfloat162*)&hv;
    float inv[8] = {__frcp_rn(ra.x), __frcp_rn(ra.y), __frcp_rn(ra.z), __frcp_rn(ra.w),
                    __frcp_rn(rb.x), __frcp_rn(rb.y), __frcp_rn(rb.z), __frcp_rn(rb.w)};
#pragma unroll
    for (int j = 0; j < 4; j++) {
        float v0 = __bfloat162float(h2[j].x) * inv[2 * j];
        float v1 = __bfloat162float(h2[j].y) * inv[2 * j + 1];
        h2[j] = __floats2bfloat162_rn(v0, v1);
    }
    *(uint4*)&g_h[i8] = hv;
}

// ---------------------------------------------------------------------------
// K4: out[b,c,m] = gamma * sum_n h'[b,c,n] * E[b,n,m] + x[b,c,m]
// 128x128 tile, 2 CTAs/SM, 4-stage cp.async with prefetch depth 3
// (issue-after-sync), single __syncthreads per K-step. Dyn smem 75.8 KB.
// ---------------------------------------------------------------------------
#define K4_LDA 40
#define K4_LDB 136
#define K4_NSTAGE 4
#define K4_A_STAGE (128 * K4_LDA)
#define K4_B_STAGE (32 * K4_LDB)
#define K4_SMEM_BYTES ((K4_NSTAGE * (K4_A_STAGE + K4_B_STAGE)) * 2)

__global__ __launch_bounds__(256, 2)
void k4_out(const float* __restrict__ x, const float* __restrict__ gamma_p,
            float* __restrict__ out) {
    const int b  = blockIdx.z;
    const int m0 = blockIdx.x * 128;
    const int c0 = blockIdx.y * 128;

    const __nv_bfloat16* hA = g_h + (size_t)b * CDIM * NDIM;
    const __nv_bfloat16* pB = g_E + (size_t)b * NDIM * NDIM;

    extern __shared__ __nv_bfloat16 smem[];
    __nv_bfloat16* As = smem;
    __nv_bfloat16* Bs = smem + K4_NSTAGE * K4_A_STAGE;

    const int tid  = threadIdx.x;
    const int warp = tid >> 5, lane = tid & 31;
    const int wm   = warp >> 2;   // 0..1 -> 64 c-rows
    const int wn   = warp & 3;    // 0..3 -> 32 m-cols

    float acc[4][4][4];
#pragma unroll
    for (int mt = 0; mt < 4; mt++)
#pragma unroll
        for (int nt = 0; nt < 4; nt++)
#pragma unroll
            for (int q = 0; q < 4; q++) acc[mt][nt][q] = 0.f;

    auto issue = [&](int kt) {
        const int buf = kt & (K4_NSTAGE - 1), k0 = kt * 32;
        __nv_bfloat16* Ab = As + buf * K4_A_STAGE;
        __nv_bfloat16* Bb = Bs + buf * K4_B_STAGE;
#pragma unroll
        for (int r = 0; r < 2; r++) {
            int idx = tid + r * 256;
            {
                int row = idx >> 2, c8 = (idx & 3) * 8;
                uint32_t d = (uint32_t)__cvta_generic_to_shared(&Ab[row * K4_LDA + c8]);
                CP_ASYNC16(d, &hA[(size_t)(c0 + row) * NDIM + k0 + c8]);
            }
            {
                int row = idx >> 4, c8 = (idx & 15) * 8;
                uint32_t d = (uint32_t)__cvta_generic_to_shared(&Bb[row * K4_LDB + c8]);
                CP_ASYNC16(d, &pB[(size_t)(k0 + row) * NDIM + m0 + c8]);
            }
        }
        CP_COMMIT;
    };

    auto compute = [&](int buf) {
        const __nv_bfloat16* Ab = As + buf * K4_A_STAGE;
        const __nv_bfloat16* Bb = Bs + buf * K4_B_STAGE;
#pragma unroll
        for (int ks = 0; ks < 2; ks++) {
            uint32_t af[4][4], bfr[4][2];
#pragma unroll
            for (int mt = 0; mt < 4; mt++) {
                uint32_t addr = (uint32_t)__cvta_generic_to_shared(
                    &Ab[(wm * 64 + mt * 16 + (lane & 15)) * K4_LDA + ks * 16 + (lane >> 4) * 8]);
                LDSM_X4(af[mt][0], af[mt][1], af[mt][2], af[mt][3], addr);
            }
#pragma unroll
            for (int np = 0; np < 2; np++) {
                uint32_t addr = (uint32_t)__cvta_generic_to_shared(
                    &Bb[(ks * 16 + (lane & 15)) * K4_LDB + wn * 32 + np * 16 + (lane >> 4) * 8]);
                uint32_t r0, r1, r2, r3;
                LDSM_X4T(r0, r1, r2, r3, addr);
                bfr[2 * np][0] = r0;     bfr[2 * np][1] = r1;
                bfr[2 * np + 1][0] = r2; bfr[2 * np + 1][1] = r3;
            }
#pragma unroll
            for (int mt = 0; mt < 4; mt++)
#pragma unroll
                for (int nt = 0; nt < 4; nt++)
                    MMA16816(acc[mt][nt], af[mt], bfr[nt][0], bfr[nt][1]);
        }
    };

    const int KT = NDIM / 32;   // 128
    issue(0);
    issue(1);
    issue(2);
    for (int kt = 0; kt < KT; kt++) {
        // complete group kt (groups kt+1, kt+2 may stay in flight)
        if (kt + 2 < KT)      { CP_WAIT(2); }
        else if (kt + 1 < KT) { CP_WAIT(1); }
        else                  { CP_WAIT(0); }
        __syncthreads();
        if (kt + 3 < KT) issue(kt + 3);   // post-sync: buf (kt-1)&3 reuse is safe
        compute(kt & (K4_NSTAGE - 1));
    }

    const float gma = gamma_p[0];
#pragma unroll
    for (int mt = 0; mt < 4; mt++) {
#pragma unroll
        for (int nt = 0; nt < 4; nt++) {
            int row = c0 + wm * 64 + mt * 16 + (lane >> 2);
            int col = m0 + wn * 32 + nt * 8 + (lane & 3) * 2;
            size_t o0_ = ((size_t)b * CDIM + row) * NDIM + col;
            size_t o1_ = o0_ + (size_t)8 * NDIM;
            float2 x0 = *(const float2*)&x[o0_];
            float2 x1 = *(const float2*)&x[o1_];
            float2 r0 = make_float2(gma * acc[mt][nt][0] + x0.x, gma * acc[mt][nt][1] + x0.y);
            float2 r1 = make_float2(gma * acc[mt][nt][2] + x1.x, gma * acc[mt][nt][3] + x1.y);
            *(float2*)&out[o0_] = r0;
            *(float2*)&out[o1_] = r1;
        }
    }
}

// ---------------------------------------------------------------------------
extern "C" void kernel_launch(void* const* d_in, const int* in_sizes, int n_in,
                              void* d_out, int out_size) {
    const float* x     = (const float*)d_in[0];
    const float* Wf    = (const float*)d_in[1];
    const float* bf    = (const float*)d_in[2];
    const float* Wg    = (const float*)d_in[3];
    const float* bg    = (const float*)d_in[4];
    const float* Wh    = (const float*)d_in[5];
    const float* bh    = (const float*)d_in[6];
    const float* gamma = (const float*)d_in[7];
    float* out = (float*)d_out;

    cudaFuncSetAttribute(k4_out, cudaFuncAttributeMaxDynamicSharedMemorySize,
                         K4_SMEM_BYTES);
    cudaFuncSetAttribute(k23_single, cudaFuncAttributeMaxDynamicSharedMemorySize,
                         FJ_SMEM_BYTES);

    kPrep<<<(BATCH * CDIM * NDIM) / (256 * 4), 256>>>(x, Wf, Wg, Wh);
    k1_tc<<<dim3(NDIM / 128, 5, BATCH), 256>>>(bf, bg, bh);
    k23_single<<<dim3(2, NDIM / 128, BATCH), 256, FJ_SMEM_BYTES>>>();
    kh_scale<<<(int)(((size_t)BATCH * CDIM * NDIM) / (256 * 8)), 256>>>();
    k4_out<<<dim3(NDIM / 128, CDIM / 128, BATCH), 256, K4_SMEM_BYTES>>>(x, gamma, out);
}

// round 10
// speedup vs baseline: 1.0463x; 1.0463x over previous
#include <cuda_runtime.h>
#include <cuda_bf16.h>
#include <cstdint>

#define BATCH 4
#define CDIM 256
#define NDIM 4096
#define SM_SHIFT 20.0f

// ---------------- scratch (__device__ globals; no allocs allowed) ----------
__device__ __nv_bfloat16 g_fT_hi[(size_t)BATCH * NDIM * 32];
__device__ __nv_bfloat16 g_fT_lo[(size_t)BATCH * NDIM * 32];
__device__ __nv_bfloat16 g_g_hi [(size_t)BATCH * 32 * NDIM];
__device__ __nv_bfloat16 g_g_lo [(size_t)BATCH * 32 * NDIM];
__device__ __nv_bfloat16 g_h    [(size_t)BATCH * CDIM * NDIM]; // h, later h/r
__device__ __nv_bfloat16 g_E    [(size_t)BATCH * NDIM * NDIM]; // exp(S-20) bf16
__device__ float         g_r    [(size_t)BATCH * NDIM];        // row sums

// ---------------- asm helpers ----------------------------------------------
#define CP_ASYNC16(dst, src) \
    asm volatile("cp.async.cg.shared.global [%0], [%1], 16;\n" ::"r"(dst), "l"(src))
#define CP_COMMIT asm volatile("cp.async.commit_group;\n")
#define CP_WAIT(n) asm volatile("cp.async.wait_group %0;\n" ::"n"(n))

#define LDSM_X4(r0, r1, r2, r3, addr)                                          \
    asm volatile("ldmatrix.sync.aligned.m8n8.x4.shared.b16 {%0,%1,%2,%3}, [%4];" \
                 : "=r"(r0), "=r"(r1), "=r"(r2), "=r"(r3) : "r"(addr))
#define LDSM_X4T(r0, r1, r2, r3, addr)                                         \
    asm volatile("ldmatrix.sync.aligned.m8n8.x4.trans.shared.b16 {%0,%1,%2,%3}, [%4];" \
                 : "=r"(r0), "=r"(r1), "=r"(r2), "=r"(r3) : "r"(addr))

#define MMA16816(d, a, b0, b1)                                                 \
    asm volatile(                                                              \
        "mma.sync.aligned.m16n8k16.row.col.f32.bf16.bf16.f32 "                 \
        "{%0,%1,%2,%3}, {%4,%5,%6,%7}, {%8,%9}, {%0,%1,%2,%3};"                \
        : "+f"(d[0]), "+f"(d[1]), "+f"(d[2]), "+f"(d[3])                       \
        : "r"(a[0]), "r"(a[1]), "r"(a[2]), "r"(a[3]), "r"(b0), "r"(b1))

__device__ __forceinline__ void split_hl(float v, __nv_bfloat16& hi, __nv_bfloat16& lo) {
    hi = __float2bfloat16(v);
    lo = __float2bfloat16(v - __bfloat162float(hi));
}

// ---------------------------------------------------------------------------
__global__ __launch_bounds__(256)
void kR_init() {
    g_r[blockIdx.x * 256 + threadIdx.x] = 0.f;
}

// ---------------------------------------------------------------------------
// k1_tc: projection on tensor cores with in-kernel fp32->bf16 hi/lo split.
// Loads x and W fp32 via register double-buffering; converts to hi/lo bf16 in
// single-buffered smem tiles (2 syncs/step, 8 K-steps). Same split values as
// the old kX/kW pre-pass -> bit-identical numerics, minus 96MB of traffic.
// o<32 -> f^T hi/lo, o in [32,64) -> g hi/lo, o>=64 -> h bf16.
// ---------------------------------------------------------------------------
#define P_LDA 40
#define P_LDB 136

__global__ __launch_bounds__(256)
void k1_tc(const float* __restrict__ x,
           const float* __restrict__ Wf, const float* __restrict__ bf,
           const float* __restrict__ Wg, const float* __restrict__ bg,
           const float* __restrict__ Wh, const float* __restrict__ bh) {
    const int b  = blockIdx.z;
    const int o0 = blockIdx.y * 64;
    const int n0 = blockIdx.x * 128;

    __shared__ __nv_bfloat16 Whs[64 * P_LDA];
    __shared__ __nv_bfloat16 Wls[64 * P_LDA];
    __shared__ __nv_bfloat16 Xhs[32 * P_LDB];
    __shared__ __nv_bfloat16 Xls[32 * P_LDB];

    const int tid = threadIdx.x, warp = tid >> 5, lane = tid & 31;
    const int wm = warp >> 2, wn = warp & 3;

    float acc[2][4][4];
#pragma unroll
    for (int mt = 0; mt < 2; mt++)
#pragma unroll
        for (int nt = 0; nt < 4; nt++)
#pragma unroll
            for (int q = 0; q < 4; q++) acc[mt][nt][q] = 0.f;

    float4 xr[4], wr[2];

    auto prefetch = [&](int kt) {
        const int k0 = kt * 32;
#pragma unroll
        for (int r = 0; r < 4; r++) {
            int idx = tid + r * 256;
            int row = idx >> 5, col4 = (idx & 31) * 4;
            xr[r] = *(const float4*)&x[((size_t)b * CDIM + k0 + row) * NDIM + n0 + col4];
        }
#pragma unroll
        for (int r = 0; r < 2; r++) {
            int idx = tid + r * 256;
            int row = idx >> 3, col4 = (idx & 7) * 4;
            int o   = o0 + row;
            const float* wrow = (o < 32) ? (Wf + (size_t)o * CDIM)
                              : (o < 64) ? (Wg + (size_t)(o - 32) * CDIM)
                                         : (Wh + (size_t)(o - 64) * CDIM);
            wr[r] = *(const float4*)&wrow[k0 + col4];
        }
    };

    auto store_tiles = [&]() {
#pragma unroll
        for (int r = 0; r < 4; r++) {
            int idx = tid + r * 256;
            int row = idx >> 5, col4 = (idx & 31) * 4;
            __nv_bfloat16 h0, l0, h1, l1, h2, l2, h3, l3;
            split_hl(xr[r].x, h0, l0); split_hl(xr[r].y, h1, l1);
            split_hl(xr[r].z, h2, l2); split_hl(xr[r].w, h3, l3);
            __nv_bfloat162* ph = (__nv_bfloat162*)&Xhs[row * P_LDB + col4];
            __nv_bfloat162* pl = (__nv_bfloat162*)&Xls[row * P_LDB + col4];
            ph[0] = __nv_bfloat162{h0, h1}; ph[1] = __nv_bfloat162{h2, h3};
            pl[0] = __nv_bfloat162{l0, l1}; pl[1] = __nv_bfloat162{l2, l3};
        }
#pragma unroll
        for (int r = 0; r < 2; r++) {
            int idx = tid + r * 256;
            int row = idx >> 3, col4 = (idx & 7) * 4;
            __nv_bfloat16 h0, l0, h1, l1, h2, l2, h3, l3;
            split_hl(wr[r].x, h0, l0); split_hl(wr[r].y, h1, l1);
            split_hl(wr[r].z, h2, l2); split_hl(wr[r].w, h3, l3);
            __nv_bfloat162* ph = (__nv_bfloat162*)&Whs[row * P_LDA + col4];
            __nv_bfloat162* pl = (__nv_bfloat162*)&Wls[row * P_LDA + col4];
            ph[0] = __nv_bfloat162{h0, h1}; ph[1] = __nv_bfloat162{h2, h3};
            pl[0] = __nv_bfloat162{l0, l1}; pl[1] = __nv_bfloat162{l2, l3};
        }
    };

    auto compute = [&]() {
#pragma unroll
        for (int ks = 0; ks < 2; ks++) {
            uint32_t ah[2][4], al[2][4], bh[4][2], bl[4][2];
#pragma unroll
            for (int mt = 0; mt < 2; mt++) {
                uint32_t ad = (uint32_t)__cvta_generic_to_shared(
                    &Whs[(wm * 32 + mt * 16 + (lane & 15)) * P_LDA + ks * 16 + (lane >> 4) * 8]);
                LDSM_X4(ah[mt][0], ah[mt][1], ah[mt][2], ah[mt][3], ad);
                uint32_t ad2 = (uint32_t)__cvta_generic_to_shared(
                    &Wls[(wm * 32 + mt * 16 + (lane & 15)) * P_LDA + ks * 16 + (lane >> 4) * 8]);
                LDSM_X4(al[mt][0], al[mt][1], al[mt][2], al[mt][3], ad2);
            }
#pragma unroll
            for (int np = 0; np < 2; np++) {
                uint32_t r0, r1, r2, r3;
                uint32_t bd = (uint32_t)__cvta_generic_to_shared(
                    &Xhs[(ks * 16 + (lane & 15)) * P_LDB + wn * 32 + np * 16 + (lane >> 4) * 8]);
                LDSM_X4T(r0, r1, r2, r3, bd);
                bh[2 * np][0] = r0;     bh[2 * np][1] = r1;
                bh[2 * np + 1][0] = r2; bh[2 * np + 1][1] = r3;
                uint32_t bd2 = (uint32_t)__cvta_generic_to_shared(
                    &Xls[(ks * 16 + (lane & 15)) * P_LDB + wn * 32 + np * 16 + (lane >> 4) * 8]);
                LDSM_X4T(r0, r1, r2, r3, bd2);
                bl[2 * np][0] = r0;     bl[2 * np][1] = r1;
                bl[2 * np + 1][0] = r2; bl[2 * np + 1][1] = r3;
            }
#pragma unroll
            for (int mt = 0; mt < 2; mt++)
#pragma unroll
                for (int nt = 0; nt < 4; nt++) {
                    MMA16816(acc[mt][nt], ah[mt], bh[nt][0], bh[nt][1]);
                    MMA16816(acc[mt][nt], ah[mt], bl[nt][0], bl[nt][1]);
                    MMA16816(acc[mt][nt], al[mt], bh[nt][0], bh[nt][1]);
                }
        }
    };

    const int KT = CDIM / 32;   // 8
    prefetch(0);
    for (int kt = 0; kt < KT; kt++) {
        store_tiles();
        if (kt + 1 < KT) prefetch(kt + 1);
        __syncthreads();
        compute();
        __syncthreads();
    }

#pragma unroll
    for (int mt = 0; mt < 2; mt++) {
#pragma unroll
        for (int nt = 0; nt < 4; nt++) {
#pragma unroll
            for (int half = 0; half < 2; half++) {
                int o = o0 + wm * 32 + mt * 16 + (lane >> 2) + half * 8;
                int n = n0 + wn * 32 + nt * 8 + (lane & 3) * 2;
                float v0 = acc[mt][nt][half * 2];
                float v1 = acc[mt][nt][half * 2 + 1];
                if (o < 32) {
                    float bias = bf[o];
                    __nv_bfloat16 h0, l0, h1, l1;
                    split_hl(v0 + bias, h0, l0);
                    split_hl(v1 + bias, h1, l1);
                    size_t base = (size_t)(b * NDIM + n) * 32 + o;
                    g_fT_hi[base] = h0;      g_fT_lo[base] = l0;
                    g_fT_hi[base + 32] = h1; g_fT_lo[base + 32] = l1;
                } else if (o < 64) {
                    float bias = bg[o - 32];
                    __nv_bfloat16 h0, l0, h1, l1;
                    split_hl(v0 + bias, h0, l0);
                    split_hl(v1 + bias, h1, l1);
                    size_t base = ((size_t)b * 32 + (o - 32)) * NDIM + n;
                    *(__nv_bfloat162*)&g_g_hi[base] = __nv_bfloat162{h0, h1};
                    *(__nv_bfloat162*)&g_g_lo[base] = __nv_bfloat162{l0, l1};
                } else {
                    float bias = bh[o - 64];
                    size_t base = ((size_t)b * CDIM + (o - 64)) * NDIM + n;
                    *(__nv_bfloat162*)&g_h[base] =
                        __floats2bfloat162_rn(v0 + bias, v1 + bias);
                }
            }
        }
    }
}

// ---------------------------------------------------------------------------
// k23_single: one pass, E + row sums (exact R7 version). grid (2, 32, B).
// ---------------------------------------------------------------------------
#define FJ_LDA 40
#define FJ_LDB 136

__global__ __launch_bounds__(256)
void k23_single() {
    const int b    = blockIdx.z;
    const int n0   = blockIdx.y * 128;
    const int part = blockIdx.x;           // m chunks [part*16, part*16+16)

    __shared__ __nv_bfloat16 Ahs[128 * FJ_LDA];
    __shared__ __nv_bfloat16 Ghs[2][32 * FJ_LDB];
    __shared__ __nv_bfloat16 Gls[2][32 * FJ_LDB];

    const int tid = threadIdx.x, wid = tid >> 5, lane = tid & 31;

    const __nv_bfloat16* fh = g_fT_hi + (size_t)(b * NDIM + n0) * 32;
    const __nv_bfloat16* fl = g_fT_lo + (size_t)(b * NDIM + n0) * 32;
    const __nv_bfloat16* gh = g_g_hi + (size_t)b * 32 * NDIM;
    const __nv_bfloat16* gl = g_g_lo + (size_t)b * 32 * NDIM;

    auto issue = [&](int mc) {
        const int buf = mc & 1, m0 = mc * 128;
#pragma unroll
        for (int r = 0; r < 2; r++) {
            int idx = tid + r * 256;
            int row = idx >> 4, c8 = (idx & 15) * 8;
            uint32_t dh = (uint32_t)__cvta_generic_to_shared(&Ghs[buf][row * FJ_LDB + c8]);
            CP_ASYNC16(dh, &gh[(size_t)row * NDIM + m0 + c8]);
            uint32_t dl = (uint32_t)__cvta_generic_to_shared(&Gls[buf][row * FJ_LDB + c8]);
            CP_ASYNC16(dl, &gl[(size_t)row * NDIM + m0 + c8]);
        }
        CP_COMMIT;
    };

    const int mc0 = part * 16, mc1 = mc0 + 16;
    issue(mc0);

    uint32_t ah[2][4], al[2][4];
#pragma unroll
    for (int r = 0; r < 2; r++) {
        int idx = tid + r * 256;
        int row = idx >> 2, c8 = (idx & 3) * 8;
        *(uint4*)&Ahs[row * FJ_LDA + c8] = *(const uint4*)&fh[row * 32 + c8];
    }
    __syncthreads();
#pragma unroll
    for (int kc = 0; kc < 2; kc++) {
        uint32_t addr = (uint32_t)__cvta_generic_to_shared(
            &Ahs[(wid * 16 + (lane & 15)) * FJ_LDA + kc * 16 + (lane >> 4) * 8]);
        LDSM_X4(ah[kc][0], ah[kc][1], ah[kc][2], ah[kc][3], addr);
    }
    __syncthreads();
#pragma unroll
    for (int r = 0; r < 2; r++) {
        int idx = tid + r * 256;
        int row = idx >> 2, c8 = (idx & 3) * 8;
        *(uint4*)&Ahs[row * FJ_LDA + c8] = *(const uint4*)&fl[row * 32 + c8];
    }
    __syncthreads();
#pragma unroll
    for (int kc = 0; kc < 2; kc++) {
        uint32_t addr = (uint32_t)__cvta_generic_to_shared(
            &Ahs[(wid * 16 + (lane & 15)) * FJ_LDA + kc * 16 + (lane >> 4) * 8]);
        LDSM_X4(al[kc][0], al[kc][1], al[kc][2], al[kc][3], addr);
    }
    __syncthreads();

    __nv_bfloat16* Eb = g_E + (size_t)b * NDIM * NDIM;
    const int row0 = n0 + wid * 16 + (lane >> 2);
    const int colb = (lane & 3) * 2;

    float s0 = 0.f, s8 = 0.f;
    for (int mc = mc0; mc < mc1; mc++) {
        if (mc + 1 < mc1) issue(mc + 1);
        if (mc + 1 < mc1) { CP_WAIT(1); } else { CP_WAIT(0); }
        __syncthreads();

        const int buf = mc & 1;
        float acc[16][4];
#pragma unroll
        for (int nt = 0; nt < 16; nt++)
#pragma unroll
            for (int q = 0; q < 4; q++) acc[nt][q] = 0.f;
#pragma unroll
        for (int kc = 0; kc < 2; kc++) {
#pragma unroll
            for (int np = 0; np < 8; np++) {
                uint32_t bh[4], bl[4];
                uint32_t addr_h = (uint32_t)__cvta_generic_to_shared(
                    &Ghs[buf][(kc * 16 + (lane & 15)) * FJ_LDB + np * 16 + (lane >> 4) * 8]);
                LDSM_X4T(bh[0], bh[1], bh[2], bh[3], addr_h);
                uint32_t addr_l = (uint32_t)__cvta_generic_to_shared(
                    &Gls[buf][(kc * 16 + (lane & 15)) * FJ_LDB + np * 16 + (lane >> 4) * 8]);
                LDSM_X4T(bl[0], bl[1], bl[2], bl[3], addr_l);
#pragma unroll
                for (int t = 0; t < 2; t++) {
                    const int nt = np * 2 + t;
                    MMA16816(acc[nt], ah[kc], bh[2 * t], bh[2 * t + 1]);
                    MMA16816(acc[nt], ah[kc], bl[2 * t], bl[2 * t + 1]);
                    MMA16816(acc[nt], al[kc], bh[2 * t], bh[2 * t + 1]);
                }
            }
        }

        const int m0 = mc * 128;
#pragma unroll
        for (int nt = 0; nt < 16; nt++) {
            float e0 = __expf(acc[nt][0] - SM_SHIFT);
            float e1 = __expf(acc[nt][1] - SM_SHIFT);
            float e2 = __expf(acc[nt][2] - SM_SHIFT);
            float e3 = __expf(acc[nt][3] - SM_SHIFT);
            s0 += e0 + e1;
            s8 += e2 + e3;
            *reinterpret_cast<__nv_bfloat162*>(
                &Eb[(size_t)row0 * NDIM + m0 + nt * 8 + colb]) = __floats2bfloat162_rn(e0, e1);
            *reinterpret_cast<__nv_bfloat162*>(
                &Eb[(size_t)(row0 + 8) * NDIM + m0 + nt * 8 + colb]) = __floats2bfloat162_rn(e2, e3);
        }
        __syncthreads();
    }

    s0 += __shfl_xor_sync(0xffffffffu, s0, 1);
    s0 += __shfl_xor_sync(0xffffffffu, s0, 2);
    s8 += __shfl_xor_sync(0xffffffffu, s8, 1);
    s8 += __shfl_xor_sync(0xffffffffu, s8, 2);
    if ((lane & 3) == 0) {
        atomicAdd(&g_r[(size_t)b * NDIM + row0], s0);
        atomicAdd(&g_r[(size_t)b * NDIM + row0 + 8], s8);
    }
}

// ---------------------------------------------------------------------------
// kh_scale: h[b,c,n] *= 1/r[b,n]  (in place).
// ---------------------------------------------------------------------------
__global__ __launch_bounds__(256)
void kh_scale() {
    size_t i8 = ((size_t)blockIdx.x * 256 + threadIdx.x) * 8;
    int n = (int)(i8 & (NDIM - 1));
    int b = (int)(i8 >> 20);
    const float* rp = &g_r[(size_t)b * NDIM + n];
    float4 ra = *(const float4*)rp;
    float4 rb = *(const float4*)(rp + 4);
    uint4 hv = *(uint4*)&g_h[i8];
    __nv_bfloat162* h2 = (__nv_bfloat162*)&hv;
    float inv[8] = {__frcp_rn(ra.x), __frcp_rn(ra.y), __frcp_rn(ra.z), __frcp_rn(ra.w),
                    __frcp_rn(rb.x), __frcp_rn(rb.y), __frcp_rn(rb.z), __frcp_rn(rb.w)};
#pragma unroll
    for (int j = 0; j < 4; j++) {
        float v0 = __bfloat162float(h2[j].x) * inv[2 * j];
        float v1 = __bfloat162float(h2[j].y) * inv[2 * j + 1];
        h2[j] = __floats2bfloat162_rn(v0, v1);
    }
    *(uint4*)&g_h[i8] = hv;
}

// ---------------------------------------------------------------------------
// K4: out[b,c,m] = gamma * sum_n h'[b,c,n] * E[b,n,m] + x[b,c,m]
// Exact R7 version: 128x128 tile, 2 CTAs/SM, 4-stage cp.async (issue-before-
// wait, depth 2), single __syncthreads per K-step. Dyn smem 75.8 KB.
// ---------------------------------------------------------------------------
#define K4_LDA 40
#define K4_LDB 136
#define K4_NSTAGE 4
#define K4_A_STAGE (128 * K4_LDA)
#define K4_B_STAGE (32 * K4_LDB)
#define K4_SMEM_BYTES ((K4_NSTAGE * (K4_A_STAGE + K4_B_STAGE)) * 2)

__global__ __launch_bounds__(256, 2)
void k4_out(const float* __restrict__ x, const float* __restrict__ gamma_p,
            float* __restrict__ out) {
    const int b  = blockIdx.z;
    const int m0 = blockIdx.x * 128;
    const int c0 = blockIdx.y * 128;

    const __nv_bfloat16* hA = g_h + (size_t)b * CDIM * NDIM;
    const __nv_bfloat16* pB = g_E + (size_t)b * NDIM * NDIM;

    extern __shared__ __nv_bfloat16 smem[];
    __nv_bfloat16* As = smem;
    __nv_bfloat16* Bs = smem + K4_NSTAGE * K4_A_STAGE;

    const int tid  = threadIdx.x;
    const int warp = tid >> 5, lane = tid & 31;
    const int wm   = warp >> 2;
    const int wn   = warp & 3;

    float acc[4][4][4];
#pragma unroll
    for (int mt = 0; mt < 4; mt++)
#pragma unroll
        for (int nt = 0; nt < 4; nt++)
#pragma unroll
            for (int q = 0; q < 4; q++) acc[mt][nt][q] = 0.f;

    auto issue = [&](int kt) {
        const int buf = kt & (K4_NSTAGE - 1), k0 = kt * 32;
        __nv_bfloat16* Ab = As + buf * K4_A_STAGE;
        __nv_bfloat16* Bb = Bs + buf * K4_B_STAGE;
#pragma unroll
        for (int r = 0; r < 2; r++) {
            int idx = tid + r * 256;
            {
                int row = idx >> 2, c8 = (idx & 3) * 8;
                uint32_t d = (uint32_t)__cvta_generic_to_shared(&Ab[row * K4_LDA + c8]);
                CP_ASYNC16(d, &hA[(size_t)(c0 + row) * NDIM + k0 + c8]);
            }
            {
                int row = idx >> 4, c8 = (idx & 15) * 8;
                uint32_t d = (uint32_t)__cvta_generic_to_shared(&Bb[row * K4_LDB + c8]);
                CP_ASYNC16(d, &pB[(size_t)(k0 + row) * NDIM + m0 + c8]);
            }
        }
        CP_COMMIT;
    };

    auto compute = [&](int buf) {
        const __nv_bfloat16* Ab = As + buf * K4_A_STAGE;
        const __nv_bfloat16* Bb = Bs + buf * K4_B_STAGE;
#pragma unroll
        for (int ks = 0; ks < 2; ks++) {
            uint32_t af[4][4], bfr[4][2];
#pragma unroll
            for (int mt = 0; mt < 4; mt++) {
                uint32_t addr = (uint32_t)__cvta_generic_to_shared(
                    &Ab[(wm * 64 + mt * 16 + (lane & 15)) * K4_LDA + ks * 16 + (lane >> 4) * 8]);
                LDSM_X4(af[mt][0], af[mt][1], af[mt][2], af[mt][3], addr);
            }
#pragma unroll
            for (int np = 0; np < 2; np++) {
                uint32_t addr = (uint32_t)__cvta_generic_to_shared(
                    &Bb[(ks * 16 + (lane & 15)) * K4_LDB + wn * 32 + np * 16 + (lane >> 4) * 8]);
                uint32_t r0, r1, r2, r3;
                LDSM_X4T(r0, r1, r2, r3, addr);
                bfr[2 * np][0] = r0;     bfr[2 * np][1] = r1;
                bfr[2 * np + 1][0] = r2; bfr[2 * np + 1][1] = r3;
            }
#pragma unroll
            for (int mt = 0; mt < 4; mt++)
#pragma unroll
                for (int nt = 0; nt < 4; nt++)
                    MMA16816(acc[mt][nt], af[mt], bfr[nt][0], bfr[nt][1]);
        }
    };

    const int KT = NDIM / 32;   // 128
    issue(0);
    issue(1);
    for (int kt = 0; kt < KT; kt++) {
        if (kt + 2 < KT) { issue(kt + 2); CP_WAIT(2); } else { CP_WAIT(0); }
        __syncthreads();
        compute(kt & (K4_NSTAGE - 1));
    }

    const float gma = gamma_p[0];
#pragma unroll
    for (int mt = 0; mt < 4; mt++) {
#pragma unroll
        for (int nt = 0; nt < 4; nt++) {
            int row = c0 + wm * 64 + mt * 16 + (lane >> 2);
            int col = m0 + wn * 32 + nt * 8 + (lane & 3) * 2;
            size_t o0_ = ((size_t)b * CDIM + row) * NDIM + col;
            size_t o1_ = o0_ + (size_t)8 * NDIM;
            float2 x0 = *(const float2*)&x[o0_];
            float2 x1 = *(const float2*)&x[o1_];
            float2 r0 = make_float2(gma * acc[mt][nt][0] + x0.x, gma * acc[mt][nt][1] + x0.y);
            float2 r1 = make_float2(gma * acc[mt][nt][2] + x1.x, gma * acc[mt][nt][3] + x1.y);
            *(float2*)&out[o0_] = r0;
            *(float2*)&out[o1_] = r1;
        }
    }
}

// ---------------------------------------------------------------------------
extern "C" void kernel_launch(void* const* d_in, const int* in_sizes, int n_in,
                              void* d_out, int out_size) {
    const float* x     = (const float*)d_in[0];
    const float* Wf    = (const float*)d_in[1];
    const float* bf    = (const float*)d_in[2];
    const float* Wg    = (const float*)d_in[3];
    const float* bg    = (const float*)d_in[4];
    const float* Wh    = (const float*)d_in[5];
    const float* bh    = (const float*)d_in[6];
    const float* gamma = (const float*)d_in[7];
    float* out = (float*)d_out;

    cudaFuncSetAttribute(k4_out, cudaFuncAttributeMaxDynamicSharedMemorySize,
                         K4_SMEM_BYTES);

    kR_init<<<(BATCH * NDIM) / 256, 256>>>();
    k1_tc<<<dim3(NDIM / 128, 5, BATCH), 256>>>(x, Wf, bf, Wg, bg, Wh, bh);
    k23_single<<<dim3(2, NDIM / 128, BATCH), 256>>>();
    kh_scale<<<(int)(((size_t)BATCH * CDIM * NDIM) / (256 * 8)), 256>>>();
    k4_out<<<dim3(NDIM / 128, CDIM / 128, BATCH), 256, K4_SMEM_BYTES>>>(x, gamma, out);
}

// round 11
// speedup vs baseline: 1.1176x; 1.0681x over previous
#include <cuda_runtime.h>
#include <cuda_bf16.h>
#include <cstdint>

#define BATCH 4
#define CDIM 256
#define NDIM 4096
#define SM_SHIFT 20.0f

// ---------------- scratch (__device__ globals; no allocs allowed) ----------
__device__ __nv_bfloat16 g_fT_hi[(size_t)BATCH * NDIM * 32];
__device__ __nv_bfloat16 g_fT_lo[(size_t)BATCH * NDIM * 32];
__device__ __nv_bfloat16 g_g_hi [(size_t)BATCH * 32 * NDIM];
__device__ __nv_bfloat16 g_h    [(size_t)BATCH * CDIM * NDIM]; // h, later h/r
__device__ __nv_bfloat16 g_E    [(size_t)BATCH * NDIM * NDIM]; // exp(S-20) bf16
__device__ float         g_r    [(size_t)BATCH * NDIM];        // row sums

// ---------------- asm helpers ----------------------------------------------
#define CP_ASYNC16(dst, src) \
    asm volatile("cp.async.cg.shared.global [%0], [%1], 16;\n" ::"r"(dst), "l"(src))
#define CP_COMMIT asm volatile("cp.async.commit_group;\n")
#define CP_WAIT(n) asm volatile("cp.async.wait_group %0;\n" ::"n"(n))

#define LDSM_X4(r0, r1, r2, r3, addr)                                          \
    asm volatile("ldmatrix.sync.aligned.m8n8.x4.shared.b16 {%0,%1,%2,%3}, [%4];" \
                 : "=r"(r0), "=r"(r1), "=r"(r2), "=r"(r3) : "r"(addr))
#define LDSM_X4T(r0, r1, r2, r3, addr)                                         \
    asm volatile("ldmatrix.sync.aligned.m8n8.x4.trans.shared.b16 {%0,%1,%2,%3}, [%4];" \
                 : "=r"(r0), "=r"(r1), "=r"(r2), "=r"(r3) : "r"(addr))

#define MMA16816(d, a, b0, b1)                                                 \
    asm volatile(                                                              \
        "mma.sync.aligned.m16n8k16.row.col.f32.bf16.bf16.f32 "                 \
        "{%0,%1,%2,%3}, {%4,%5,%6,%7}, {%8,%9}, {%0,%1,%2,%3};"                \
        : "+f"(d[0]), "+f"(d[1]), "+f"(d[2]), "+f"(d[3])                       \
        : "r"(a[0]), "r"(a[1]), "r"(a[2]), "r"(a[3]), "r"(b0), "r"(b1))

__device__ __forceinline__ void split_hl(float v, __nv_bfloat16& hi, __nv_bfloat16& lo) {
    hi = __float2bfloat16(v);
    lo = __float2bfloat16(v - __bfloat162float(hi));
}

// ---------------------------------------------------------------------------
__global__ __launch_bounds__(256)
void kR_init() {
    g_r[blockIdx.x * 256 + threadIdx.x] = 0.f;
}

// ---------------------------------------------------------------------------
// k1_tc: projection on tensor cores with in-kernel fp32->bf16 hi/lo split.
// o<32 -> f^T hi/lo, o in [32,64) -> g hi ONLY, o>=64 -> h bf16.
// ---------------------------------------------------------------------------
#define P_LDA 40
#define P_LDB 136

__global__ __launch_bounds__(256)
void k1_tc(const float* __restrict__ x,
           const float* __restrict__ Wf, const float* __restrict__ bf,
           const float* __restrict__ Wg, const float* __restrict__ bg,
           const float* __restrict__ Wh, const float* __restrict__ bh) {
    const int b  = blockIdx.z;
    const int o0 = blockIdx.y * 64;
    const int n0 = blockIdx.x * 128;

    __shared__ __nv_bfloat16 Whs[64 * P_LDA];
    __shared__ __nv_bfloat16 Wls[64 * P_LDA];
    __shared__ __nv_bfloat16 Xhs[32 * P_LDB];
    __shared__ __nv_bfloat16 Xls[32 * P_LDB];

    const int tid = threadIdx.x, warp = tid >> 5, lane = tid & 31;
    const int wm = warp >> 2, wn = warp & 3;

    float acc[2][4][4];
#pragma unroll
    for (int mt = 0; mt < 2; mt++)
#pragma unroll
        for (int nt = 0; nt < 4; nt++)
#pragma unroll
            for (int q = 0; q < 4; q++) acc[mt][nt][q] = 0.f;

    float4 xr[4], wr[2];

    auto prefetch = [&](int kt) {
        const int k0 = kt * 32;
#pragma unroll
        for (int r = 0; r < 4; r++) {
            int idx = tid + r * 256;
            int row = idx >> 5, col4 = (idx & 31) * 4;
            xr[r] = *(const float4*)&x[((size_t)b * CDIM + k0 + row) * NDIM + n0 + col4];
        }
#pragma unroll
        for (int r = 0; r < 2; r++) {
            int idx = tid + r * 256;
            int row = idx >> 3, col4 = (idx & 7) * 4;
            int o   = o0 + row;
            const float* wrow = (o < 32) ? (Wf + (size_t)o * CDIM)
                              : (o < 64) ? (Wg + (size_t)(o - 32) * CDIM)
                                         : (Wh + (size_t)(o - 64) * CDIM);
            wr[r] = *(const float4*)&wrow[k0 + col4];
        }
    };

    auto store_tiles = [&]() {
#pragma unroll
        for (int r = 0; r < 4; r++) {
            int idx = tid + r * 256;
            int row = idx >> 5, col4 = (idx & 31) * 4;
            __nv_bfloat16 h0, l0, h1, l1, h2, l2, h3, l3;
            split_hl(xr[r].x, h0, l0); split_hl(xr[r].y, h1, l1);
            split_hl(xr[r].z, h2, l2); split_hl(xr[r].w, h3, l3);
            __nv_bfloat162* ph = (__nv_bfloat162*)&Xhs[row * P_LDB + col4];
            __nv_bfloat162* pl = (__nv_bfloat162*)&Xls[row * P_LDB + col4];
            ph[0] = __nv_bfloat162{h0, h1}; ph[1] = __nv_bfloat162{h2, h3};
            pl[0] = __nv_bfloat162{l0, l1}; pl[1] = __nv_bfloat162{l2, l3};
        }
#pragma unroll
        for (int r = 0; r < 2; r++) {
            int idx = tid + r * 256;
            int row = idx >> 3, col4 = (idx & 7) * 4;
            __nv_bfloat16 h0, l0, h1, l1, h2, l2, h3, l3;
            split_hl(wr[r].x, h0, l0); split_hl(wr[r].y, h1, l1);
            split_hl(wr[r].z, h2, l2); split_hl(wr[r].w, h3, l3);
            __nv_bfloat162* ph = (__nv_bfloat162*)&Whs[row * P_LDA + col4];
            __nv_bfloat162* pl = (__nv_bfloat162*)&Wls[row * P_LDA + col4];
            ph[0] = __nv_bfloat162{h0, h1}; ph[1] = __nv_bfloat162{h2, h3};
            pl[0] = __nv_bfloat162{l0, l1}; pl[1] = __nv_bfloat162{l2, l3};
        }
    };

    auto compute = [&]() {
#pragma unroll
        for (int ks = 0; ks < 2; ks++) {
            uint32_t ah[2][4], al[2][4], bh[4][2], bl[4][2];
#pragma unroll
            for (int mt = 0; mt < 2; mt++) {
                uint32_t ad = (uint32_t)__cvta_generic_to_shared(
                    &Whs[(wm * 32 + mt * 16 + (lane & 15)) * P_LDA + ks * 16 + (lane >> 4) * 8]);
                LDSM_X4(ah[mt][0], ah[mt][1], ah[mt][2], ah[mt][3], ad);
                uint32_t ad2 = (uint32_t)__cvta_generic_to_shared(
                    &Wls[(wm * 32 + mt * 16 + (lane & 15)) * P_LDA + ks * 16 + (lane >> 4) * 8]);
                LDSM_X4(al[mt][0], al[mt][1], al[mt][2], al[mt][3], ad2);
            }
#pragma unroll
            for (int np = 0; np < 2; np++) {
                uint32_t r0, r1, r2, r3;
                uint32_t bd = (uint32_t)__cvta_generic_to_shared(
                    &Xhs[(ks * 16 + (lane & 15)) * P_LDB + wn * 32 + np * 16 + (lane >> 4) * 8]);
                LDSM_X4T(r0, r1, r2, r3, bd);
                bh[2 * np][0] = r0;     bh[2 * np][1] = r1;
                bh[2 * np + 1][0] = r2; bh[2 * np + 1][1] = r3;
                uint32_t bd2 = (uint32_t)__cvta_generic_to_shared(
                    &Xls[(ks * 16 + (lane & 15)) * P_LDB + wn * 32 + np * 16 + (lane >> 4) * 8]);
                LDSM_X4T(r0, r1, r2, r3, bd2);
                bl[2 * np][0] = r0;     bl[2 * np][1] = r1;
                bl[2 * np + 1][0] = r2; bl[2 * np + 1][1] = r3;
            }
#pragma unroll
            for (int mt = 0; mt < 2; mt++)
#pragma unroll
                for (int nt = 0; nt < 4; nt++) {
                    MMA16816(acc[mt][nt], ah[mt], bh[nt][0], bh[nt][1]);
                    MMA16816(acc[mt][nt], ah[mt], bl[nt][0], bl[nt][1]);
                    MMA16816(acc[mt][nt], al[mt], bh[nt][0], bh[nt][1]);
                }
        }
    };

    const int KT = CDIM / 32;   // 8
    prefetch(0);
    for (int kt = 0; kt < KT; kt++) {
        store_tiles();
        if (kt + 1 < KT) prefetch(kt + 1);
        __syncthreads();
        compute();
        __syncthreads();
    }

#pragma unroll
    for (int mt = 0; mt < 2; mt++) {
#pragma unroll
        for (int nt = 0; nt < 4; nt++) {
#pragma unroll
            for (int half = 0; half < 2; half++) {
                int o = o0 + wm * 32 + mt * 16 + (lane >> 2) + half * 8;
                int n = n0 + wn * 32 + nt * 8 + (lane & 3) * 2;
                float v0 = acc[mt][nt][half * 2];
                float v1 = acc[mt][nt][half * 2 + 1];
                if (o < 32) {
                    float bias = bf[o];
                    __nv_bfloat16 h0, l0, h1, l1;
                    split_hl(v0 + bias, h0, l0);
                    split_hl(v1 + bias, h1, l1);
                    size_t base = (size_t)(b * NDIM + n) * 32 + o;
                    g_fT_hi[base] = h0;      g_fT_lo[base] = l0;
                    g_fT_hi[base + 32] = h1; g_fT_lo[base + 32] = l1;
                } else if (o < 64) {
                    float bias = bg[o - 32];
                    size_t base = ((size_t)b * 32 + (o - 32)) * NDIM + n;
                    *(__nv_bfloat162*)&g_g_hi[base] =
                        __floats2bfloat162_rn(v0 + bias, v1 + bias);
                } else {
                    float bias = bh[o - 64];
                    size_t base = ((size_t)b * CDIM + (o - 64)) * NDIM + n;
                    *(__nv_bfloat162*)&g_h[base] =
                        __floats2bfloat162_rn(v0 + bias, v1 + bias);
                }
            }
        }
    }
}

// ---------------------------------------------------------------------------
// k23_single: one pass, E + row sums. S = (f_hi + f_lo) * g_hi (2 MMA terms;
// g's lo dropped -> 1/3 fewer MMAs, half the streamed B traffic).
// grid (2, 32, B).
// ---------------------------------------------------------------------------
#define FJ_LDA 40
#define FJ_LDB 136

__global__ __launch_bounds__(256)
void k23_single() {
    const int b    = blockIdx.z;
    const int n0   = blockIdx.y * 128;
    const int part = blockIdx.x;           // m chunks [part*16, part*16+16)

    __shared__ __nv_bfloat16 Ahs[128 * FJ_LDA];
    __shared__ __nv_bfloat16 Ghs[2][32 * FJ_LDB];

    const int tid = threadIdx.x, wid = tid >> 5, lane = tid & 31;

    const __nv_bfloat16* fh = g_fT_hi + (size_t)(b * NDIM + n0) * 32;
    const __nv_bfloat16* fl = g_fT_lo + (size_t)(b * NDIM + n0) * 32;
    const __nv_bfloat16* gh = g_g_hi + (size_t)b * 32 * NDIM;

    auto issue = [&](int mc) {
        const int buf = mc & 1, m0 = mc * 128;
#pragma unroll
        for (int r = 0; r < 2; r++) {
            int idx = tid + r * 256;
            int row = idx >> 4, c8 = (idx & 15) * 8;
            uint32_t dh = (uint32_t)__cvta_generic_to_shared(&Ghs[buf][row * FJ_LDB + c8]);
            CP_ASYNC16(dh, &gh[(size_t)row * NDIM + m0 + c8]);
        }
        CP_COMMIT;
    };

    const int mc0 = part * 16, mc1 = mc0 + 16;
    issue(mc0);

    uint32_t ah[2][4], al[2][4];
#pragma unroll
    for (int r = 0; r < 2; r++) {
        int idx = tid + r * 256;
        int row = idx >> 2, c8 = (idx & 3) * 8;
        *(uint4*)&Ahs[row * FJ_LDA + c8] = *(const uint4*)&fh[row * 32 + c8];
    }
    __syncthreads();
#pragma unroll
    for (int kc = 0; kc < 2; kc++) {
        uint32_t addr = (uint32_t)__cvta_generic_to_shared(
            &Ahs[(wid * 16 + (lane & 15)) * FJ_LDA + kc * 16 + (lane >> 4) * 8]);
        LDSM_X4(ah[kc][0], ah[kc][1], ah[kc][2], ah[kc][3], addr);
    }
    __syncthreads();
#pragma unroll
    for (int r = 0; r < 2; r++) {
        int idx = tid + r * 256;
        int row = idx >> 2, c8 = (idx & 3) * 8;
        *(uint4*)&Ahs[row * FJ_LDA + c8] = *(const uint4*)&fl[row * 32 + c8];
    }
    __syncthreads();
#pragma unroll
    for (int kc = 0; kc < 2; kc++) {
        uint32_t addr = (uint32_t)__cvta_generic_to_shared(
            &Ahs[(wid * 16 + (lane & 15)) * FJ_LDA + kc * 16 + (lane >> 4) * 8]);
        LDSM_X4(al[kc][0], al[kc][1], al[kc][2], al[kc][3], addr);
    }
    __syncthreads();

    __nv_bfloat16* Eb = g_E + (size_t)b * NDIM * NDIM;
    const int row0 = n0 + wid * 16 + (lane >> 2);
    const int colb = (lane & 3) * 2;

    float s0 = 0.f, s8 = 0.f;
    for (int mc = mc0; mc < mc1; mc++) {
        if (mc + 1 < mc1) issue(mc + 1);
        if (mc + 1 < mc1) { CP_WAIT(1); } else { CP_WAIT(0); }
        __syncthreads();

        const int buf = mc & 1;
        float acc[16][4];
#pragma unroll
        for (int nt = 0; nt < 16; nt++)
#pragma unroll
            for (int q = 0; q < 4; q++) acc[nt][q] = 0.f;
#pragma unroll
        for (int kc = 0; kc < 2; kc++) {
#pragma unroll
            for (int np = 0; np < 8; np++) {
                uint32_t bh[4];
                uint32_t addr_h = (uint32_t)__cvta_generic_to_shared(
                    &Ghs[buf][(kc * 16 + (lane & 15)) * FJ_LDB + np * 16 + (lane >> 4) * 8]);
                LDSM_X4T(bh[0], bh[1], bh[2], bh[3], addr_h);
#pragma unroll
                for (int t = 0; t < 2; t++) {
                    const int nt = np * 2 + t;
                    MMA16816(acc[nt], ah[kc], bh[2 * t], bh[2 * t + 1]);
                    MMA16816(acc[nt], al[kc], bh[2 * t], bh[2 * t + 1]);
                }
            }
        }

        const int m0 = mc * 128;
#pragma unroll
        for (int nt = 0; nt < 16; nt++) {
            float e0 = __expf(acc[nt][0] - SM_SHIFT);
            float e1 = __expf(acc[nt][1] - SM_SHIFT);
            float e2 = __expf(acc[nt][2] - SM_SHIFT);
            float e3 = __expf(acc[nt][3] - SM_SHIFT);
            s0 += e0 + e1;
            s8 += e2 + e3;
            *reinterpret_cast<__nv_bfloat162*>(
                &Eb[(size_t)row0 * NDIM + m0 + nt * 8 + colb]) = __floats2bfloat162_rn(e0, e1);
            *reinterpret_cast<__nv_bfloat162*>(
                &Eb[(size_t)(row0 + 8) * NDIM + m0 + nt * 8 + colb]) = __floats2bfloat162_rn(e2, e3);
        }
        __syncthreads();
    }

    s0 += __shfl_xor_sync(0xffffffffu, s0, 1);
    s0 += __shfl_xor_sync(0xffffffffu, s0, 2);
    s8 += __shfl_xor_sync(0xffffffffu, s8, 1);
    s8 += __shfl_xor_sync(0xffffffffu, s8, 2);
    if ((lane & 3) == 0) {
        atomicAdd(&g_r[(size_t)b * NDIM + row0], s0);
        atomicAdd(&g_r[(size_t)b * NDIM + row0 + 8], s8);
    }
}

// ---------------------------------------------------------------------------
// kh_scale: h[b,c,n] *= 1/r[b,n]  (in place).
// ---------------------------------------------------------------------------
__global__ __launch_bounds__(256)
void kh_scale() {
    size_t i8 = ((size_t)blockIdx.x * 256 + threadIdx.x) * 8;
    int n = (int)(i8 & (NDIM - 1));
    int b = (int)(i8 >> 20);
    const float* rp = &g_r[(size_t)b * NDIM + n];
    float4 ra = *(const float4*)rp;
    float4 rb = *(const float4*)(rp + 4);
    uint4 hv = *(uint4*)&g_h[i8];
    __nv_bfloat162* h2 = (__nv_bfloat162*)&hv;
    float inv[8] = {__frcp_rn(ra.x), __frcp_rn(ra.y), __frcp_rn(ra.z), __frcp_rn(ra.w),
                    __frcp_rn(rb.x), __frcp_rn(rb.y), __frcp_rn(rb.z), __frcp_rn(rb.w)};
#pragma unroll
    for (int j = 0; j < 4; j++) {
        float v0 = __bfloat162float(h2[j].x) * inv[2 * j];
        float v1 = __bfloat162float(h2[j].y) * inv[2 * j + 1];
        h2[j] = __floats2bfloat162_rn(v0, v1);
    }
    *(uint4*)&g_h[i8] = hv;
}

// ---------------------------------------------------------------------------
// K4: out[b,c,m] = gamma * sum_n h'[b,c,n] * E[b,n,m] + x[b,c,m]
// 128x128 tile, 2 CTAs/SM, 4-stage cp.async, single sync per K-step.
// Grid reordered: c fastest so the two c-CTAs sharing an E tile are adjacent
// (tight L2 reuse of the 2x E read).
// ---------------------------------------------------------------------------
#define K4_LDA 40
#define K4_LDB 136
#define K4_NSTAGE 4
#define K4_A_STAGE (128 * K4_LDA)
#define K4_B_STAGE (32 * K4_LDB)
#define K4_SMEM_BYTES ((K4_NSTAGE * (K4_A_STAGE + K4_B_STAGE)) * 2)

__global__ __launch_bounds__(256, 2)
void k4_out(const float* __restrict__ x, const float* __restrict__ gamma_p,
            float* __restrict__ out) {
    const int b  = blockIdx.z;
    const int c0 = blockIdx.x * 128;   // fastest
    const int m0 = blockIdx.y * 128;

    const __nv_bfloat16* hA = g_h + (size_t)b * CDIM * NDIM;
    const __nv_bfloat16* pB = g_E + (size_t)b * NDIM * NDIM;

    extern __shared__ __nv_bfloat16 smem[];
    __nv_bfloat16* As = smem;
    __nv_bfloat16* Bs = smem + K4_NSTAGE * K4_A_STAGE;

    const int tid  = threadIdx.x;
    const int warp = tid >> 5, lane = tid & 31;
    const int wm   = warp >> 2;
    const int wn   = warp & 3;

    float acc[4][4][4];
#pragma unroll
    for (int mt = 0; mt < 4; mt++)
#pragma unroll
        for (int nt = 0; nt < 4; nt++)
#pragma unroll
            for (int q = 0; q < 4; q++) acc[mt][nt][q] = 0.f;

    auto issue = [&](int kt) {
        const int buf = kt & (K4_NSTAGE - 1), k0 = kt * 32;
        __nv_bfloat16* Ab = As + buf * K4_A_STAGE;
        __nv_bfloat16* Bb = Bs + buf * K4_B_STAGE;
#pragma unroll
        for (int r = 0; r < 2; r++) {
            int idx = tid + r * 256;
            {
                int row = idx >> 2, c8 = (idx & 3) * 8;
                uint32_t d = (uint32_t)__cvta_generic_to_shared(&Ab[row * K4_LDA + c8]);
                CP_ASYNC16(d, &hA[(size_t)(c0 + row) * NDIM + k0 + c8]);
            }
            {
                int row = idx >> 4, c8 = (idx & 15) * 8;
                uint32_t d = (uint32_t)__cvta_generic_to_shared(&Bb[row * K4_LDB + c8]);
                CP_ASYNC16(d, &pB[(size_t)(k0 + row) * NDIM + m0 + c8]);
            }
        }
        CP_COMMIT;
    };

    auto compute = [&](int buf) {
        const __nv_bfloat16* Ab = As + buf * K4_A_STAGE;
        const __nv_bfloat16* Bb = Bs + buf * K4_B_STAGE;
#pragma unroll
        for (int ks = 0; ks < 2; ks++) {
            uint32_t af[4][4], bfr[4][2];
#pragma unroll
            for (int mt = 0; mt < 4; mt++) {
                uint32_t addr = (uint32_t)__cvta_generic_to_shared(
                    &Ab[(wm * 64 + mt * 16 + (lane & 15)) * K4_LDA + ks * 16 + (lane >> 4) * 8]);
                LDSM_X4(af[mt][0], af[mt][1], af[mt][2], af[mt][3], addr);
            }
#pragma unroll
            for (int np = 0; np < 2; np++) {
                uint32_t addr = (uint32_t)__cvta_generic_to_shared(
                    &Bb[(ks * 16 + (lane & 15)) * K4_LDB + wn * 32 + np * 16 + (lane >> 4) * 8]);
                uint32_t r0, r1, r2, r3;
                LDSM_X4T(r0, r1, r2, r3, addr);
                bfr[2 * np][0] = r0;     bfr[2 * np][1] = r1;
                bfr[2 * np + 1][0] = r2; bfr[2 * np + 1][1] = r3;
            }
#pragma unroll
            for (int mt = 0; mt < 4; mt++)
#pragma unroll
                for (int nt = 0; nt < 4; nt++)
                    MMA16816(acc[mt][nt], af[mt], bfr[nt][0], bfr[nt][1]);
        }
    };

    const int KT = NDIM / 32;   // 128
    issue(0);
    issue(1);
    for (int kt = 0; kt < KT; kt++) {
        if (kt + 2 < KT) { issue(kt + 2); CP_WAIT(2); } else { CP_WAIT(0); }
        __syncthreads();
        compute(kt & (K4_NSTAGE - 1));
    }

    const float gma = gamma_p[0];
#pragma unroll
    for (int mt = 0; mt < 4; mt++) {
#pragma unroll
        for (int nt = 0; nt < 4; nt++) {
            int row = c0 + wm * 64 + mt * 16 + (lane >> 2);
            int col = m0 + wn * 32 + nt * 8 + (lane & 3) * 2;
            size_t o0_ = ((size_t)b * CDIM + row) * NDIM + col;
            size_t o1_ = o0_ + (size_t)8 * NDIM;
            float2 x0 = *(const float2*)&x[o0_];
            float2 x1 = *(const float2*)&x[o1_];
            float2 r0 = make_float2(gma * acc[mt][nt][0] + x0.x, gma * acc[mt][nt][1] + x0.y);
            float2 r1 = make_float2(gma * acc[mt][nt][2] + x1.x, gma * acc[mt][nt][3] + x1.y);
            *(float2*)&out[o0_] = r0;
            *(float2*)&out[o1_] = r1;
        }
    }
}

// ---------------------------------------------------------------------------
extern "C" void kernel_launch(void* const* d_in, const int* in_sizes, int n_in,
                              void* d_out, int out_size) {
    const float* x     = (const float*)d_in[0];
    const float* Wf    = (const float*)d_in[1];
    const float* bf    = (const float*)d_in[2];
    const float* Wg    = (const float*)d_in[3];
    const float* bg    = (const float*)d_in[4];
    const float* Wh    = (const float*)d_in[5];
    const float* bh    = (const float*)d_in[6];
    const float* gamma = (const float*)d_in[7];
    float* out = (float*)d_out;

    cudaFuncSetAttribute(k4_out, cudaFuncAttributeMaxDynamicSharedMemorySize,
                         K4_SMEM_BYTES);

    kR_init<<<(BATCH * NDIM) / 256, 256>>>();
    k1_tc<<<dim3(NDIM / 128, 5, BATCH), 256>>>(x, Wf, bf, Wg, bg, Wh, bh);
    k23_single<<<dim3(2, NDIM / 128, BATCH), 256>>>();
    kh_scale<<<(int)(((size_t)BATCH * CDIM * NDIM) / (256 * 8)), 256>>>();
    k4_out<<<dim3(CDIM / 128, NDIM / 128, BATCH), 256, K4_SMEM_BYTES>>>(x, gamma, out);
}